// round 4
// baseline (speedup 1.0000x reference)
#include <cuda_runtime.h>

// ---------------- problem-size constants (max) ----------------
#define N_MAX 100000
#define E_MAX 1600000

// ---------------- scratch (device globals; no allocation allowed) ----------
__device__ float g_deg [N_MAX];            // dinv
__device__ float g_y   [N_MAX * 64];       // dinv * (x @ W)
__device__ float g_h   [N_MAX * 64];       // layer output (h1 then h2)
__device__ float g_t1  [N_MAX * 128];      // MLP hidden 1
__device__ float g_t2  [N_MAX * 64];       // MLP hidden 2
__device__ int   g_cnt [N_MAX];            // dst histogram
__device__ int   g_rp  [N_MAX + 1];        // CSR row pointers (by dst)
__device__ int   g_wp  [N_MAX];            // fill write pointers
__device__ int   g_eidx[E_MAX];            // src ids grouped by dst
__device__ int   g_bsum[256];              // scan block partials

// ---------------- CSR build ----------------
__global__ void k_zero(int* cnt, int N) {
    int i = blockIdx.x * blockDim.x + threadIdx.x;
    if (i < N) cnt[i] = 0;
}

__global__ void k_hist(const int* __restrict__ dst, int* __restrict__ cnt, int E) {
    int i = blockIdx.x * blockDim.x + threadIdx.x;
    if (i < E) atomicAdd(&cnt[dst[i]], 1);
}

// block b scans 1024 elements (256 threads x 4); writes local-exclusive prefix
// into rp and the block total into bsum[b]
__global__ void k_scan1(const int* __restrict__ cnt, int* __restrict__ rp,
                        int* __restrict__ bsum, int N) {
    __shared__ int wsum[8];
    __shared__ int btot;
    int t = threadIdx.x, lane = t & 31, w = t >> 5;
    int base = blockIdx.x * 1024 + t * 4;
    int v0 = (base + 0 < N) ? cnt[base + 0] : 0;
    int v1 = (base + 1 < N) ? cnt[base + 1] : 0;
    int v2 = (base + 2 < N) ? cnt[base + 2] : 0;
    int v3 = (base + 3 < N) ? cnt[base + 3] : 0;
    int s = v0 + v1 + v2 + v3;
    int x = s;
    #pragma unroll
    for (int o = 1; o < 32; o <<= 1) {
        int y = __shfl_up_sync(0xffffffffu, x, o);
        if (lane >= o) x += y;
    }
    if (lane == 31) wsum[w] = x;
    __syncthreads();
    if (t == 0) {
        int a = 0;
        #pragma unroll
        for (int i = 0; i < 8; ++i) { int tmp = wsum[i]; wsum[i] = a; a += tmp; }
        btot = a;
    }
    __syncthreads();
    int off = (x - s) + wsum[w];
    if (base + 0 < N) rp[base + 0] = off;
    if (base + 1 < N) rp[base + 1] = off + v0;
    if (base + 2 < N) rp[base + 2] = off + v0 + v1;
    if (base + 3 < N) rp[base + 3] = off + v0 + v1 + v2;
    if (t == 0) bsum[blockIdx.x] = btot;
}

// parallel exclusive scan of bsum (nB <= 128), one block of 128 threads
__global__ void k_scan2(int* bsum, int nB) {
    __shared__ int ws[4];
    int t = threadIdx.x, lane = t & 31, w = t >> 5;
    int v = (t < nB) ? bsum[t] : 0;
    int x = v;
    #pragma unroll
    for (int o = 1; o < 32; o <<= 1) {
        int y = __shfl_up_sync(0xffffffffu, x, o);
        if (lane >= o) x += y;
    }
    if (lane == 31) ws[w] = x;
    __syncthreads();
    if (t == 0) {
        int a = 0;
        #pragma unroll
        for (int i = 0; i < 4; ++i) { int tmp = ws[i]; ws[i] = a; a += tmp; }
    }
    __syncthreads();
    if (t < nB) bsum[t] = (x - v) + ws[w];
}

// finalize rowptr, reset write pointers, compute dinv = rsqrt(cnt + 2)
__global__ void k_scan3(const int* __restrict__ cnt, int* __restrict__ rp,
                        int* __restrict__ wp, float* __restrict__ dinv,
                        const int* __restrict__ bsum, int N, int E) {
    int i = blockIdx.x * blockDim.x + threadIdx.x;
    if (i < N) {
        int v = rp[i] + bsum[i >> 10];
        rp[i] = v;
        wp[i] = v;
        dinv[i] = rsqrtf((float)cnt[i] + 2.0f);
    }
    if (i == 0) rp[N] = E;
}

__global__ void k_fill(const int* __restrict__ src, const int* __restrict__ dst,
                       int* __restrict__ wp, int* __restrict__ eidx, int E) {
    int i = blockIdx.x * blockDim.x + threadIdx.x;
    if (i < E) {
        int pos = atomicAdd(&wp[dst[i]], 1);
        eidx[pos] = src[i];
    }
}

// ---------------- fused gather + epilogue ----------------
// one warp per dst node: h[i] = relu(dinv[i] * (sum_{s in nbrs(i)} y[s] + 2*y[i]) + b)
__global__ void k_gather(const float* __restrict__ y, const int* __restrict__ rp,
                         const int* __restrict__ eidx, const float* __restrict__ dinv,
                         const float* __restrict__ b, float* __restrict__ h, int N) {
    int warp = (blockIdx.x * blockDim.x + threadIdx.x) >> 5;
    int lane = threadIdx.x & 31;
    if (warp >= N) return;
    const int c = lane * 2;
    int beg = rp[warp], end = rp[warp + 1];

    float2 a0 = *(const float2*)(y + (size_t)warp * 64 + c);
    a0.x *= 2.0f; a0.y *= 2.0f;
    float2 a1 = make_float2(0.f, 0.f);

    for (int j0 = beg; j0 < end; j0 += 32) {
        int myj = j0 + lane;
        int sreg = (myj < end) ? eidx[myj] : 0;
        int n = min(32, end - j0);
        int t = 0;
        for (; t + 1 < n; t += 2) {
            int s0 = __shfl_sync(0xffffffffu, sreg, t);
            int s1 = __shfl_sync(0xffffffffu, sreg, t + 1);
            float2 v0 = *(const float2*)(y + (size_t)s0 * 64 + c);
            float2 v1 = *(const float2*)(y + (size_t)s1 * 64 + c);
            a0.x += v0.x; a0.y += v0.y;
            a1.x += v1.x; a1.y += v1.y;
        }
        if (t < n) {
            int s0 = __shfl_sync(0xffffffffu, sreg, t);
            float2 v0 = *(const float2*)(y + (size_t)s0 * 64 + c);
            a0.x += v0.x; a0.y += v0.y;
        }
    }
    float d = dinv[warp];
    float2 o;
    o.x = fmaxf(d * (a0.x + a1.x) + b[c],     0.0f);
    o.y = fmaxf(d * (a0.y + a1.y) + b[c + 1], 0.0f);
    *(float2*)(h + (size_t)warp * 64 + c) = o;
}

// ---------------- register-blocked fp32 GEMM (8x8 per thread) ----------------
// OUT[N,M] = post( scale?(dinv[row]) * (X[N,K] @ W[K,M]) + bias? ), relu?
// DUAL: X row = concat(X0 row [64], X1 row [64]) (K must be 128)
template<int K, int M, bool DUAL, bool PRESCALE, bool BIAS, bool RELU>
__global__ void __launch_bounds__(256, 1)
k_gemm(const float* __restrict__ X0, const float* __restrict__ X1,
       const float* __restrict__ W,  const float* __restrict__ bias,
       const float* __restrict__ dinv, float* __restrict__ OUT, int N) {
    constexpr int CG   = M / 8;          // col groups (8 cols per thread)
    constexpr int RG   = 256 / CG;       // row groups (8 rows per thread)
    constexpr int TILE = RG * 8;         // rows per block tile
    constexpr int XSTR = K + 1;          // padded (odd) x row stride

    extern __shared__ float sm[];
    float* Ws = sm;                      // K*M
    float* Xs = sm + K * M;              // TILE * XSTR

    for (int i = threadIdx.x; i < K * M; i += 256) Ws[i] = W[i];

    const int cg = threadIdx.x % CG;
    const int rg = threadIdx.x / CG;
    const int numTiles = (N + TILE - 1) / TILE;

    for (int tile = blockIdx.x; tile < numTiles; tile += gridDim.x) {
        const int row0 = tile * TILE;
        __syncthreads();
        // stage X tile (coalesced read, conflict-free write)
        for (int i = threadIdx.x; i < TILE * K; i += 256) {
            int r = i / K, c = i % K;
            int gr = row0 + r;
            float v = 0.f;
            if (gr < N) {
                if (!DUAL) v = X0[(size_t)gr * K + c];
                else       v = (c < 64) ? X0[(size_t)gr * 64 + c]
                                        : X1[(size_t)gr * 64 + (c - 64)];
            }
            Xs[r * XSTR + c] = v;
        }
        __syncthreads();

        float acc[8][8];
        #pragma unroll
        for (int j = 0; j < 8; ++j)
            #pragma unroll
            for (int q = 0; q < 8; ++q) acc[j][q] = 0.f;

        const float* xbase = Xs + (rg * 8) * XSTR;
        const float* wbase = Ws + cg * 8;

        #pragma unroll 4
        for (int k = 0; k < K; ++k) {
            float4 wa = *(const float4*)(wbase + k * M);
            float4 wb = *(const float4*)(wbase + k * M + 4);
            float x[8];
            #pragma unroll
            for (int j = 0; j < 8; ++j) x[j] = xbase[j * XSTR + k];
            #pragma unroll
            for (int j = 0; j < 8; ++j) {
                acc[j][0] += x[j] * wa.x; acc[j][1] += x[j] * wa.y;
                acc[j][2] += x[j] * wa.z; acc[j][3] += x[j] * wa.w;
                acc[j][4] += x[j] * wb.x; acc[j][5] += x[j] * wb.y;
                acc[j][6] += x[j] * wb.z; acc[j][7] += x[j] * wb.w;
            }
        }

        #pragma unroll
        for (int j = 0; j < 8; ++j) {
            int gr = row0 + rg * 8 + j;
            if (gr >= N) continue;
            float s = PRESCALE ? dinv[gr] : 1.0f;
            float4 o0, o1;
            o0.x = acc[j][0]; o0.y = acc[j][1]; o0.z = acc[j][2]; o0.w = acc[j][3];
            o1.x = acc[j][4]; o1.y = acc[j][5]; o1.z = acc[j][6]; o1.w = acc[j][7];
            if (PRESCALE) {
                o0.x *= s; o0.y *= s; o0.z *= s; o0.w *= s;
                o1.x *= s; o1.y *= s; o1.z *= s; o1.w *= s;
            }
            if (BIAS) {
                float4 ba4 = *(const float4*)(bias + cg * 8);
                float4 bb4 = *(const float4*)(bias + cg * 8 + 4);
                o0.x += ba4.x; o0.y += ba4.y; o0.z += ba4.z; o0.w += ba4.w;
                o1.x += bb4.x; o1.y += bb4.y; o1.z += bb4.z; o1.w += bb4.w;
            }
            if (RELU) {
                o0.x = fmaxf(o0.x, 0.f); o0.y = fmaxf(o0.y, 0.f);
                o0.z = fmaxf(o0.z, 0.f); o0.w = fmaxf(o0.w, 0.f);
                o1.x = fmaxf(o1.x, 0.f); o1.y = fmaxf(o1.y, 0.f);
                o1.z = fmaxf(o1.z, 0.f); o1.w = fmaxf(o1.w, 0.f);
            }
            float* op = OUT + (size_t)gr * M + cg * 8;
            *(float4*)(op)     = o0;
            *(float4*)(op + 4) = o1;
        }
    }
}

// ---------------- JAX partitionable threefry2x32 (key = [0, 42]) ----------
__device__ __forceinline__ unsigned rotl32(unsigned v, int r) {
    return (v << r) | (v >> (32 - r));
}

__device__ __forceinline__ uint2 threefry(unsigned c0, unsigned c1) {
    const unsigned k0 = 0u, k1 = 42u;
    const unsigned k2 = k0 ^ k1 ^ 0x1BD11BDAu;
    unsigned x0 = c0 + k0, x1 = c1 + k1;
#define TF_RND(r) { x0 += x1; x1 = rotl32(x1, r); x1 ^= x0; }
    TF_RND(13) TF_RND(15) TF_RND(26) TF_RND(6)
    x0 += k1; x1 += k2 + 1u;
    TF_RND(17) TF_RND(29) TF_RND(16) TF_RND(24)
    x0 += k2; x1 += k0 + 2u;
    TF_RND(13) TF_RND(15) TF_RND(26) TF_RND(6)
    x0 += k0; x1 += k1 + 3u;
    TF_RND(17) TF_RND(29) TF_RND(16) TF_RND(24)
    x0 += k1; x1 += k2 + 4u;
    TF_RND(13) TF_RND(15) TF_RND(26) TF_RND(6)
    x0 += k2; x1 += k0 + 5u;
#undef TF_RND
    return make_uint2(x0, x1);
}

__device__ __forceinline__ unsigned tf_bits_part(unsigned i) {
    uint2 o = threefry(0u, i);
    return o.x ^ o.y;
}

__device__ __forceinline__ float bits_to_uniform(unsigned b) {
    float f = __uint_as_float((b >> 9) | 0x3f800000u) - 1.0f;
    f = f + 1e-20f;
    return fmaxf(f, 1e-20f);
}

// ---------------- final: t2 @ Wo + bo -> sigmoid -> gumbel hard sample -----
__global__ void k_final(const float* __restrict__ t2, const float* __restrict__ Wo,
                        const float* __restrict__ bo, float* __restrict__ out, int N) {
    __shared__ float ws[64];
    if (threadIdx.x < 64) ws[threadIdx.x] = Wo[threadIdx.x];
    __syncthreads();

    int warp = (blockIdx.x * blockDim.x + threadIdx.x) >> 5;
    int lane = threadIdx.x & 31;
    if (warp >= N) return;

    const float* row = t2 + (size_t)warp * 64;
    float s = row[lane] * ws[lane] + row[lane + 32] * ws[lane + 32];
    #pragma unroll
    for (int o = 16; o; o >>= 1) s += __shfl_xor_sync(0xffffffffu, s, o);

    float p = 1.0f / (1.0f + expf(-(s + bo[0])));

    float g = 0.0f;
    if (lane < 2) {
        unsigned f = 2u * (unsigned)warp + (unsigned)lane;
        float u = bits_to_uniform(tf_bits_part(f));
        g = -logf(-logf(u));
    }
    float g0 = __shfl_sync(0xffffffffu, g, 0);
    float g1 = __shfl_sync(0xffffffffu, g, 1);

    if (lane == 0) {
        out[warp]     = p;
        out[N + warp] = ((p + g1) > ((1.0f - p) + g0)) ? 1.0f : 0.0f;
    }
}

// ---------------- launch ----------------
extern "C" void kernel_launch(void* const* d_in, const int* in_sizes, int n_in,
                              void* d_out, int out_size) {
    const float* rep = (const float*)d_in[0];
    const int*   ei  = (const int*)  d_in[1];
    const float* W1  = (const float*)d_in[2];
    const float* b1  = (const float*)d_in[3];
    const float* W2  = (const float*)d_in[4];
    const float* b2  = (const float*)d_in[5];
    const float* Wa  = (const float*)d_in[6];
    const float* ba  = (const float*)d_in[7];
    const float* Wb  = (const float*)d_in[8];
    const float* bb  = (const float*)d_in[9];
    const float* Wo  = (const float*)d_in[10];
    const float* bo  = (const float*)d_in[11];
    float* out = (float*)d_out;

    int N = in_sizes[0] / 64;
    int E = in_sizes[1] / 2;
    if (N > N_MAX || E > E_MAX) return;
    const int* src = ei;
    const int* dst = ei + E;

    float *dinv, *y, *h, *t1, *t2;
    int *cnt, *rp, *wp, *eidx, *bsum;
    cudaGetSymbolAddress((void**)&dinv, g_deg);
    cudaGetSymbolAddress((void**)&y,    g_y);
    cudaGetSymbolAddress((void**)&h,    g_h);
    cudaGetSymbolAddress((void**)&t1,   g_t1);
    cudaGetSymbolAddress((void**)&t2,   g_t2);
    cudaGetSymbolAddress((void**)&cnt,  g_cnt);
    cudaGetSymbolAddress((void**)&rp,   g_rp);
    cudaGetSymbolAddress((void**)&wp,   g_wp);
    cudaGetSymbolAddress((void**)&eidx, g_eidx);
    cudaGetSymbolAddress((void**)&bsum, g_bsum);

    // dynamic smem sizes: Ws K*M + Xs TILE*(K+1)
    const int SM_G64  = (64 * 64   + 256 * 65)  * 4;   // ~81 KB
    const int SM_MLP1 = (128 * 128 + 128 * 129) * 4;   // ~129 KB
    const int SM_MLP2 = (128 * 64  + 256 * 129) * 4;   // ~161 KB
    cudaFuncSetAttribute((const void*)k_gemm<64,64,false,true,false,false>,
                         cudaFuncAttributeMaxDynamicSharedMemorySize, SM_G64);
    cudaFuncSetAttribute((const void*)k_gemm<128,128,true ,false,true ,true >,
                         cudaFuncAttributeMaxDynamicSharedMemorySize, SM_MLP1);
    cudaFuncSetAttribute((const void*)k_gemm<128,64 ,false,false,true ,true >,
                         cudaFuncAttributeMaxDynamicSharedMemorySize, SM_MLP2);

    const int TB = 256;
    int gN    = (N + TB - 1) / TB;
    int gEdge = (E + TB - 1) / TB;
    int nB    = (N + 1023) / 1024;
    int gWarp = (N * 32 + TB - 1) / TB;

    // ---- CSR build (also yields exact degree -> dinv) ----
    k_zero <<<gN,    TB>>>(cnt, N);
    k_hist <<<gEdge, TB>>>(dst, cnt, E);
    k_scan1<<<nB,    256>>>(cnt, rp, bsum, N);
    k_scan2<<<1,     128>>>(bsum, nB);
    k_scan3<<<gN,    TB>>>(cnt, rp, wp, dinv, bsum, N, E);
    k_fill <<<gEdge, TB>>>(src, dst, wp, eidx, E);

    int t256 = (N + 255) / 256;   // gemm64 / MLP2 tiles
    int t128 = (N + 127) / 128;   // MLP1 tiles

    // ---- GCN layer 1 ----
    k_gemm<64,64,false,true,false,false><<<t256, TB, SM_G64>>>(rep, nullptr, W1, nullptr, dinv, y, N);
    k_gather<<<gWarp, TB>>>(y, rp, eidx, dinv, b1, h, N);

    // ---- GCN layer 2 ----
    k_gemm<64,64,false,true,false,false><<<t256, TB, SM_G64>>>(h, nullptr, W2, nullptr, dinv, y, N);
    k_gather<<<gWarp, TB>>>(y, rp, eidx, dinv, b2, h, N);

    // ---- MLP head: z = [rep, h2] ----
    k_gemm<128,128,true ,false,true,true><<<t128, TB, SM_MLP1>>>(rep, h, Wa, ba, nullptr, t1, N);
    k_gemm<128,64 ,false,false,true,true><<<t256, TB, SM_MLP2>>>(t1, nullptr, Wb, bb, nullptr, t2, N);

    // ---- final projection + sigmoid + gumbel straight-through ----
    int gFin = (N + 7) / 8;
    k_final<<<gFin, TB>>>(t2, Wo, bo, out, N);
}

// round 5
// speedup vs baseline: 1.5305x; 1.5305x over previous
#include <cuda_runtime.h>

// ---------------- problem-size constants (max) ----------------
#define N_MAX 100000
#define E_MAX 1600000

// ---------------- scratch (device globals; no allocation allowed) ----------
__device__ float g_deg [N_MAX];            // dinv
__device__ float g_y   [N_MAX * 64];       // dinv * (x @ W)
__device__ float g_h   [N_MAX * 64];       // layer output (h1 then h2)
__device__ float g_t1  [N_MAX * 128];      // MLP hidden 1
__device__ float g_t2  [N_MAX * 64];       // MLP hidden 2
__device__ int   g_cnt [N_MAX];            // dst histogram
__device__ int   g_rp  [N_MAX + 1];        // CSR row pointers (by dst)
__device__ int   g_wp  [N_MAX];            // fill write pointers
__device__ int   g_eidx[E_MAX];            // src ids grouped by dst
__device__ int   g_bsum[256];              // scan block partials

// ---------------- CSR build ----------------
__global__ void k_zero(int* cnt, int N) {
    int i = blockIdx.x * blockDim.x + threadIdx.x;
    if (i < N) cnt[i] = 0;
}

__global__ void k_hist(const int* __restrict__ dst, int* __restrict__ cnt, int E) {
    int i = blockIdx.x * blockDim.x + threadIdx.x;
    if (i < E) atomicAdd(&cnt[dst[i]], 1);
}

// block b scans 1024 elements (256 threads x 4)
__global__ void k_scan1(const int* __restrict__ cnt, int* __restrict__ rp,
                        int* __restrict__ bsum, int N) {
    __shared__ int wsum[8];
    __shared__ int btot;
    int t = threadIdx.x, lane = t & 31, w = t >> 5;
    int base = blockIdx.x * 1024 + t * 4;
    int v0 = (base + 0 < N) ? cnt[base + 0] : 0;
    int v1 = (base + 1 < N) ? cnt[base + 1] : 0;
    int v2 = (base + 2 < N) ? cnt[base + 2] : 0;
    int v3 = (base + 3 < N) ? cnt[base + 3] : 0;
    int s = v0 + v1 + v2 + v3;
    int x = s;
    #pragma unroll
    for (int o = 1; o < 32; o <<= 1) {
        int y = __shfl_up_sync(0xffffffffu, x, o);
        if (lane >= o) x += y;
    }
    if (lane == 31) wsum[w] = x;
    __syncthreads();
    if (t == 0) {
        int a = 0;
        #pragma unroll
        for (int i = 0; i < 8; ++i) { int tmp = wsum[i]; wsum[i] = a; a += tmp; }
        btot = a;
    }
    __syncthreads();
    int off = (x - s) + wsum[w];
    if (base + 0 < N) rp[base + 0] = off;
    if (base + 1 < N) rp[base + 1] = off + v0;
    if (base + 2 < N) rp[base + 2] = off + v0 + v1;
    if (base + 3 < N) rp[base + 3] = off + v0 + v1 + v2;
    if (t == 0) bsum[blockIdx.x] = btot;
}

// parallel exclusive scan of bsum (nB <= 128)
__global__ void k_scan2(int* bsum, int nB) {
    __shared__ int ws[4];
    int t = threadIdx.x, lane = t & 31, w = t >> 5;
    int v = (t < nB) ? bsum[t] : 0;
    int x = v;
    #pragma unroll
    for (int o = 1; o < 32; o <<= 1) {
        int y = __shfl_up_sync(0xffffffffu, x, o);
        if (lane >= o) x += y;
    }
    if (lane == 31) ws[w] = x;
    __syncthreads();
    if (t == 0) {
        int a = 0;
        #pragma unroll
        for (int i = 0; i < 4; ++i) { int tmp = ws[i]; ws[i] = a; a += tmp; }
    }
    __syncthreads();
    if (t < nB) bsum[t] = (x - v) + ws[w];
}

__global__ void k_scan3(const int* __restrict__ cnt, int* __restrict__ rp,
                        int* __restrict__ wp, float* __restrict__ dinv,
                        const int* __restrict__ bsum, int N, int E) {
    int i = blockIdx.x * blockDim.x + threadIdx.x;
    if (i < N) {
        int v = rp[i] + bsum[i >> 10];
        rp[i] = v;
        wp[i] = v;
        dinv[i] = rsqrtf((float)cnt[i] + 2.0f);
    }
    if (i == 0) rp[N] = E;
}

__global__ void k_fill(const int* __restrict__ src, const int* __restrict__ dst,
                       int* __restrict__ wp, int* __restrict__ eidx, int E) {
    int i = blockIdx.x * blockDim.x + threadIdx.x;
    if (i < E) {
        int pos = atomicAdd(&wp[dst[i]], 1);
        eidx[pos] = src[i];
    }
}

// ---------------- fused gather + epilogue ----------------
__global__ void k_gather(const float* __restrict__ y, const int* __restrict__ rp,
                         const int* __restrict__ eidx, const float* __restrict__ dinv,
                         const float* __restrict__ b, float* __restrict__ h, int N) {
    int warp = (blockIdx.x * blockDim.x + threadIdx.x) >> 5;
    int lane = threadIdx.x & 31;
    if (warp >= N) return;
    const int c = lane * 2;
    int beg = rp[warp], end = rp[warp + 1];

    float2 a0 = *(const float2*)(y + (size_t)warp * 64 + c);
    a0.x *= 2.0f; a0.y *= 2.0f;
    float2 a1 = make_float2(0.f, 0.f);

    for (int j0 = beg; j0 < end; j0 += 32) {
        int myj = j0 + lane;
        int sreg = (myj < end) ? eidx[myj] : 0;
        int n = min(32, end - j0);
        int t = 0;
        for (; t + 1 < n; t += 2) {
            int s0 = __shfl_sync(0xffffffffu, sreg, t);
            int s1 = __shfl_sync(0xffffffffu, sreg, t + 1);
            float2 v0 = *(const float2*)(y + (size_t)s0 * 64 + c);
            float2 v1 = *(const float2*)(y + (size_t)s1 * 64 + c);
            a0.x += v0.x; a0.y += v0.y;
            a1.x += v1.x; a1.y += v1.y;
        }
        if (t < n) {
            int s0 = __shfl_sync(0xffffffffu, sreg, t);
            float2 v0 = *(const float2*)(y + (size_t)s0 * 64 + c);
            a0.x += v0.x; a0.y += v0.y;
        }
    }
    float d = dinv[warp];
    float2 o;
    o.x = fmaxf(d * (a0.x + a1.x) + b[c],     0.0f);
    o.y = fmaxf(d * (a0.y + a1.y) + b[c + 1], 0.0f);
    *(float2*)(h + (size_t)warp * 64 + c) = o;
}

// ---------------- register-blocked fp32 GEMM (4 rows x 8 cols / thread) ----
// OUT[N,M] = post( scale?(dinv[row]) * (X[N,K] @ W[K,M]) + bias? ), relu?
// DUAL: X row = concat(X0 row [64], X1 row [64]) (K must be 128)
template<int K, int M, bool DUAL, bool PRESCALE, bool BIAS, bool RELU>
__global__ void __launch_bounds__(256)
k_gemm(const float* __restrict__ X0, const float* __restrict__ X1,
       const float* __restrict__ W,  const float* __restrict__ bias,
       const float* __restrict__ dinv, float* __restrict__ OUT, int N) {
    constexpr int CG   = M / 8;          // col groups (8 cols per thread)
    constexpr int RG   = 256 / CG;       // row groups (4 rows per thread)
    constexpr int TILE = RG * 4;         // rows per block tile
    constexpr int XSTR = K + 1;          // padded (odd) x row stride

    extern __shared__ float sm[];
    float* Ws = sm;                      // K*M
    float* Xs = sm + K * M;              // TILE * XSTR

    for (int i = threadIdx.x; i < K * M; i += 256) Ws[i] = W[i];

    const int cg = threadIdx.x % CG;
    const int rg = threadIdx.x / CG;
    const int numTiles = (N + TILE - 1) / TILE;

    for (int tile = blockIdx.x; tile < numTiles; tile += gridDim.x) {
        const int row0 = tile * TILE;
        __syncthreads();
        for (int i = threadIdx.x; i < TILE * K; i += 256) {
            int r = i / K, c = i % K;
            int gr = row0 + r;
            float v = 0.f;
            if (gr < N) {
                if (!DUAL) v = X0[(size_t)gr * K + c];
                else       v = (c < 64) ? X0[(size_t)gr * 64 + c]
                                        : X1[(size_t)gr * 64 + (c - 64)];
            }
            Xs[r * XSTR + c] = v;
        }
        __syncthreads();

        float acc[4][8];
        #pragma unroll
        for (int j = 0; j < 4; ++j)
            #pragma unroll
            for (int q = 0; q < 8; ++q) acc[j][q] = 0.f;

        const float* xbase = Xs + (rg * 4) * XSTR;
        const float* wbase = Ws + cg * 8;

        #pragma unroll 4
        for (int k = 0; k < K; ++k) {
            float4 wa = *(const float4*)(wbase + k * M);
            float4 wb = *(const float4*)(wbase + k * M + 4);
            float x0 = xbase[0 * XSTR + k];
            float x1 = xbase[1 * XSTR + k];
            float x2 = xbase[2 * XSTR + k];
            float x3 = xbase[3 * XSTR + k];
            acc[0][0] += x0 * wa.x; acc[0][1] += x0 * wa.y; acc[0][2] += x0 * wa.z; acc[0][3] += x0 * wa.w;
            acc[0][4] += x0 * wb.x; acc[0][5] += x0 * wb.y; acc[0][6] += x0 * wb.z; acc[0][7] += x0 * wb.w;
            acc[1][0] += x1 * wa.x; acc[1][1] += x1 * wa.y; acc[1][2] += x1 * wa.z; acc[1][3] += x1 * wa.w;
            acc[1][4] += x1 * wb.x; acc[1][5] += x1 * wb.y; acc[1][6] += x1 * wb.z; acc[1][7] += x1 * wb.w;
            acc[2][0] += x2 * wa.x; acc[2][1] += x2 * wa.y; acc[2][2] += x2 * wa.z; acc[2][3] += x2 * wa.w;
            acc[2][4] += x2 * wb.x; acc[2][5] += x2 * wb.y; acc[2][6] += x2 * wb.z; acc[2][7] += x2 * wb.w;
            acc[3][0] += x3 * wa.x; acc[3][1] += x3 * wa.y; acc[3][2] += x3 * wa.z; acc[3][3] += x3 * wa.w;
            acc[3][4] += x3 * wb.x; acc[3][5] += x3 * wb.y; acc[3][6] += x3 * wb.z; acc[3][7] += x3 * wb.w;
        }

        #pragma unroll
        for (int j = 0; j < 4; ++j) {
            int gr = row0 + rg * 4 + j;
            if (gr >= N) continue;
            float4 o0, o1;
            o0.x = acc[j][0]; o0.y = acc[j][1]; o0.z = acc[j][2]; o0.w = acc[j][3];
            o1.x = acc[j][4]; o1.y = acc[j][5]; o1.z = acc[j][6]; o1.w = acc[j][7];
            if (PRESCALE) {
                float s = dinv[gr];
                o0.x *= s; o0.y *= s; o0.z *= s; o0.w *= s;
                o1.x *= s; o1.y *= s; o1.z *= s; o1.w *= s;
            }
            if (BIAS) {
                float4 ba4 = *(const float4*)(bias + cg * 8);
                float4 bb4 = *(const float4*)(bias + cg * 8 + 4);
                o0.x += ba4.x; o0.y += ba4.y; o0.z += ba4.z; o0.w += ba4.w;
                o1.x += bb4.x; o1.y += bb4.y; o1.z += bb4.z; o1.w += bb4.w;
            }
            if (RELU) {
                o0.x = fmaxf(o0.x, 0.f); o0.y = fmaxf(o0.y, 0.f);
                o0.z = fmaxf(o0.z, 0.f); o0.w = fmaxf(o0.w, 0.f);
                o1.x = fmaxf(o1.x, 0.f); o1.y = fmaxf(o1.y, 0.f);
                o1.z = fmaxf(o1.z, 0.f); o1.w = fmaxf(o1.w, 0.f);
            }
            float* op = OUT + (size_t)gr * M + cg * 8;
            *(float4*)(op)     = o0;
            *(float4*)(op + 4) = o1;
        }
    }
}

// ---------------- JAX partitionable threefry2x32 (key = [0, 42]) ----------
__device__ __forceinline__ unsigned rotl32(unsigned v, int r) {
    return (v << r) | (v >> (32 - r));
}

__device__ __forceinline__ uint2 threefry(unsigned c0, unsigned c1) {
    const unsigned k0 = 0u, k1 = 42u;
    const unsigned k2 = k0 ^ k1 ^ 0x1BD11BDAu;
    unsigned x0 = c0 + k0, x1 = c1 + k1;
#define TF_RND(r) { x0 += x1; x1 = rotl32(x1, r); x1 ^= x0; }
    TF_RND(13) TF_RND(15) TF_RND(26) TF_RND(6)
    x0 += k1; x1 += k2 + 1u;
    TF_RND(17) TF_RND(29) TF_RND(16) TF_RND(24)
    x0 += k2; x1 += k0 + 2u;
    TF_RND(13) TF_RND(15) TF_RND(26) TF_RND(6)
    x0 += k0; x1 += k1 + 3u;
    TF_RND(17) TF_RND(29) TF_RND(16) TF_RND(24)
    x0 += k1; x1 += k2 + 4u;
    TF_RND(13) TF_RND(15) TF_RND(26) TF_RND(6)
    x0 += k2; x1 += k0 + 5u;
#undef TF_RND
    return make_uint2(x0, x1);
}

__device__ __forceinline__ unsigned tf_bits_part(unsigned i) {
    uint2 o = threefry(0u, i);
    return o.x ^ o.y;
}

__device__ __forceinline__ float bits_to_uniform(unsigned b) {
    float f = __uint_as_float((b >> 9) | 0x3f800000u) - 1.0f;
    f = f + 1e-20f;
    return fmaxf(f, 1e-20f);
}

// ---------------- final: t2 @ Wo + bo -> sigmoid -> gumbel hard sample -----
__global__ void k_final(const float* __restrict__ t2, const float* __restrict__ Wo,
                        const float* __restrict__ bo, float* __restrict__ out, int N) {
    __shared__ float ws[64];
    if (threadIdx.x < 64) ws[threadIdx.x] = Wo[threadIdx.x];
    __syncthreads();

    int warp = (blockIdx.x * blockDim.x + threadIdx.x) >> 5;
    int lane = threadIdx.x & 31;
    if (warp >= N) return;

    const float* row = t2 + (size_t)warp * 64;
    float s = row[lane] * ws[lane] + row[lane + 32] * ws[lane + 32];
    #pragma unroll
    for (int o = 16; o; o >>= 1) s += __shfl_xor_sync(0xffffffffu, s, o);

    float p = 1.0f / (1.0f + expf(-(s + bo[0])));

    float g = 0.0f;
    if (lane < 2) {
        unsigned f = 2u * (unsigned)warp + (unsigned)lane;
        float u = bits_to_uniform(tf_bits_part(f));
        g = -logf(-logf(u));
    }
    float g0 = __shfl_sync(0xffffffffu, g, 0);
    float g1 = __shfl_sync(0xffffffffu, g, 1);

    if (lane == 0) {
        out[warp]     = p;
        out[N + warp] = ((p + g1) > ((1.0f - p) + g0)) ? 1.0f : 0.0f;
    }
}

// ---------------- launch ----------------
extern "C" void kernel_launch(void* const* d_in, const int* in_sizes, int n_in,
                              void* d_out, int out_size) {
    const float* rep = (const float*)d_in[0];
    const int*   ei  = (const int*)  d_in[1];
    const float* W1  = (const float*)d_in[2];
    const float* b1  = (const float*)d_in[3];
    const float* W2  = (const float*)d_in[4];
    const float* b2  = (const float*)d_in[5];
    const float* Wa  = (const float*)d_in[6];
    const float* ba  = (const float*)d_in[7];
    const float* Wb  = (const float*)d_in[8];
    const float* bb  = (const float*)d_in[9];
    const float* Wo  = (const float*)d_in[10];
    const float* bo  = (const float*)d_in[11];
    float* out = (float*)d_out;

    int N = in_sizes[0] / 64;
    int E = in_sizes[1] / 2;
    if (N > N_MAX || E > E_MAX) return;
    const int* src = ei;
    const int* dst = ei + E;

    float *dinv, *y, *h, *t1, *t2;
    int *cnt, *rp, *wp, *eidx, *bsum;
    cudaGetSymbolAddress((void**)&dinv, g_deg);
    cudaGetSymbolAddress((void**)&y,    g_y);
    cudaGetSymbolAddress((void**)&h,    g_h);
    cudaGetSymbolAddress((void**)&t1,   g_t1);
    cudaGetSymbolAddress((void**)&t2,   g_t2);
    cudaGetSymbolAddress((void**)&cnt,  g_cnt);
    cudaGetSymbolAddress((void**)&rp,   g_rp);
    cudaGetSymbolAddress((void**)&wp,   g_wp);
    cudaGetSymbolAddress((void**)&eidx, g_eidx);
    cudaGetSymbolAddress((void**)&bsum, g_bsum);

    // dynamic smem: Ws K*M + Xs TILE*(K+1)
    const int SM_G64  = (64 * 64   + 128 * 65)  * 4;   // ~50 KB  (TILE=128)
    const int SM_MLP1 = (128 * 128 + 64  * 129) * 4;   // ~97 KB  (TILE=64)
    const int SM_MLP2 = (128 * 64  + 128 * 129) * 4;   // ~99 KB  (TILE=128)
    cudaFuncSetAttribute((const void*)k_gemm<64,64,false,true,false,false>,
                         cudaFuncAttributeMaxDynamicSharedMemorySize, SM_G64);
    cudaFuncSetAttribute((const void*)k_gemm<128,128,true ,false,true ,true >,
                         cudaFuncAttributeMaxDynamicSharedMemorySize, SM_MLP1);
    cudaFuncSetAttribute((const void*)k_gemm<128,64 ,false,false,true ,true >,
                         cudaFuncAttributeMaxDynamicSharedMemorySize, SM_MLP2);

    const int TB = 256;
    int gN    = (N + TB - 1) / TB;
    int gEdge = (E + TB - 1) / TB;
    int nB    = (N + 1023) / 1024;
    int gWarp = (N * 32 + TB - 1) / TB;

    // ---- CSR build (also yields exact degree -> dinv) ----
    k_zero <<<gN,    TB>>>(cnt, N);
    k_hist <<<gEdge, TB>>>(dst, cnt, E);
    k_scan1<<<nB,    256>>>(cnt, rp, bsum, N);
    k_scan2<<<1,     128>>>(bsum, nB);
    k_scan3<<<gN,    TB>>>(cnt, rp, wp, dinv, bsum, N, E);
    k_fill <<<gEdge, TB>>>(src, dst, wp, eidx, E);

    int t128 = (N + 127) / 128;   // gemm64 / MLP2 tiles (TILE=128)
    int t64  = (N + 63)  / 64;    // MLP1 tiles (TILE=64)

    // ---- GCN layer 1 ----
    k_gemm<64,64,false,true,false,false><<<t128, TB, SM_G64>>>(rep, nullptr, W1, nullptr, dinv, y, N);
    k_gather<<<gWarp, TB>>>(y, rp, eidx, dinv, b1, h, N);

    // ---- GCN layer 2 ----
    k_gemm<64,64,false,true,false,false><<<t128, TB, SM_G64>>>(h, nullptr, W2, nullptr, dinv, y, N);
    k_gather<<<gWarp, TB>>>(y, rp, eidx, dinv, b2, h, N);

    // ---- MLP head: z = [rep, h2] ----
    k_gemm<128,128,true ,false,true,true><<<t64,  TB, SM_MLP1>>>(rep, h, Wa, ba, nullptr, t1, N);
    k_gemm<128,64 ,false,false,true,true><<<t128, TB, SM_MLP2>>>(t1, nullptr, Wb, bb, nullptr, t2, N);

    // ---- final projection + sigmoid + gumbel straight-through ----
    int gFin = (N + 7) / 8;
    k_final<<<gFin, TB>>>(t2, Wo, bo, out, N);
}

// round 6
// speedup vs baseline: 1.9185x; 1.2535x over previous
#include <cuda_runtime.h>

// ---------------- problem-size constants (max) ----------------
#define N_MAX 100000
#define E_MAX 1600000

// ---------------- scratch (device globals; no allocation allowed) ----------
__device__ float g_deg [N_MAX];            // dinv
__device__ float g_y   [N_MAX * 64];       // dinv * (x @ W)
__device__ float g_h   [N_MAX * 64];       // layer output (h1 then h2)
__device__ float g_t1  [N_MAX * 128];      // MLP hidden 1
__device__ float g_t2  [N_MAX * 64];       // MLP hidden 2
__device__ int   g_cnt [N_MAX];            // dst histogram
__device__ int   g_rp  [N_MAX + 1];        // CSR row pointers (by dst)
__device__ int   g_wp  [N_MAX];            // fill write pointers
__device__ int   g_eidx[E_MAX];            // src ids grouped by dst
__device__ int   g_bsum[256];              // scan block partials

// ---------------- packed f32x2 helpers (sm_103a FFMA2 path) ----------------
__device__ __forceinline__ unsigned long long fma2(unsigned long long a,
                                                   unsigned long long b,
                                                   unsigned long long c) {
    unsigned long long d;
    asm("fma.rn.f32x2 %0, %1, %2, %3;" : "=l"(d) : "l"(a), "l"(b), "l"(c));
    return d;
}
__device__ __forceinline__ unsigned long long pack2(float lo, float hi) {
    unsigned long long d;
    asm("mov.b64 %0, {%1, %2};" : "=l"(d) : "f"(lo), "f"(hi));
    return d;
}
__device__ __forceinline__ void unpack2(unsigned long long v, float& lo, float& hi) {
    asm("mov.b64 {%0, %1}, %2;" : "=f"(lo), "=f"(hi) : "l"(v));
}

// ---------------- CSR build ----------------
__global__ void k_zero(int* cnt, int N) {
    int i = blockIdx.x * blockDim.x + threadIdx.x;
    if (i < N) cnt[i] = 0;
}

__global__ void k_hist(const int* __restrict__ dst, int* __restrict__ cnt, int E) {
    int i = blockIdx.x * blockDim.x + threadIdx.x;
    if (i < E) atomicAdd(&cnt[dst[i]], 1);
}

// block b scans 1024 elements (256 threads x 4)
__global__ void k_scan1(const int* __restrict__ cnt, int* __restrict__ rp,
                        int* __restrict__ bsum, int N) {
    __shared__ int wsum[8];
    __shared__ int btot;
    int t = threadIdx.x, lane = t & 31, w = t >> 5;
    int base = blockIdx.x * 1024 + t * 4;
    int v0 = (base + 0 < N) ? cnt[base + 0] : 0;
    int v1 = (base + 1 < N) ? cnt[base + 1] : 0;
    int v2 = (base + 2 < N) ? cnt[base + 2] : 0;
    int v3 = (base + 3 < N) ? cnt[base + 3] : 0;
    int s = v0 + v1 + v2 + v3;
    int x = s;
    #pragma unroll
    for (int o = 1; o < 32; o <<= 1) {
        int y = __shfl_up_sync(0xffffffffu, x, o);
        if (lane >= o) x += y;
    }
    if (lane == 31) wsum[w] = x;
    __syncthreads();
    if (t == 0) {
        int a = 0;
        #pragma unroll
        for (int i = 0; i < 8; ++i) { int tmp = wsum[i]; wsum[i] = a; a += tmp; }
        btot = a;
    }
    __syncthreads();
    int off = (x - s) + wsum[w];
    if (base + 0 < N) rp[base + 0] = off;
    if (base + 1 < N) rp[base + 1] = off + v0;
    if (base + 2 < N) rp[base + 2] = off + v0 + v1;
    if (base + 3 < N) rp[base + 3] = off + v0 + v1 + v2;
    if (t == 0) bsum[blockIdx.x] = btot;
}

// parallel exclusive scan of bsum (nB <= 128)
__global__ void k_scan2(int* bsum, int nB) {
    __shared__ int ws[4];
    int t = threadIdx.x, lane = t & 31, w = t >> 5;
    int v = (t < nB) ? bsum[t] : 0;
    int x = v;
    #pragma unroll
    for (int o = 1; o < 32; o <<= 1) {
        int y = __shfl_up_sync(0xffffffffu, x, o);
        if (lane >= o) x += y;
    }
    if (lane == 31) ws[w] = x;
    __syncthreads();
    if (t == 0) {
        int a = 0;
        #pragma unroll
        for (int i = 0; i < 4; ++i) { int tmp = ws[i]; ws[i] = a; a += tmp; }
    }
    __syncthreads();
    if (t < nB) bsum[t] = (x - v) + ws[w];
}

__global__ void k_scan3(const int* __restrict__ cnt, int* __restrict__ rp,
                        int* __restrict__ wp, float* __restrict__ dinv,
                        const int* __restrict__ bsum, int N, int E) {
    int i = blockIdx.x * blockDim.x + threadIdx.x;
    if (i < N) {
        int v = rp[i] + bsum[i >> 10];
        rp[i] = v;
        wp[i] = v;
        dinv[i] = rsqrtf((float)cnt[i] + 2.0f);
    }
    if (i == 0) rp[N] = E;
}

__global__ void k_fill(const int* __restrict__ src, const int* __restrict__ dst,
                       int* __restrict__ wp, int* __restrict__ eidx, int E) {
    int i = blockIdx.x * blockDim.x + threadIdx.x;
    if (i < E) {
        int pos = atomicAdd(&wp[dst[i]], 1);
        eidx[pos] = src[i];
    }
}

// ---------------- fused gather + epilogue ----------------
__global__ void k_gather(const float* __restrict__ y, const int* __restrict__ rp,
                         const int* __restrict__ eidx, const float* __restrict__ dinv,
                         const float* __restrict__ b, float* __restrict__ h, int N) {
    int warp = (blockIdx.x * blockDim.x + threadIdx.x) >> 5;
    int lane = threadIdx.x & 31;
    if (warp >= N) return;
    const int c = lane * 2;
    int beg = rp[warp], end = rp[warp + 1];

    float2 a0 = *(const float2*)(y + (size_t)warp * 64 + c);
    a0.x *= 2.0f; a0.y *= 2.0f;
    float2 a1 = make_float2(0.f, 0.f);

    for (int j0 = beg; j0 < end; j0 += 32) {
        int myj = j0 + lane;
        int sreg = (myj < end) ? eidx[myj] : 0;
        int n = min(32, end - j0);
        int t = 0;
        for (; t + 1 < n; t += 2) {
            int s0 = __shfl_sync(0xffffffffu, sreg, t);
            int s1 = __shfl_sync(0xffffffffu, sreg, t + 1);
            float2 v0 = *(const float2*)(y + (size_t)s0 * 64 + c);
            float2 v1 = *(const float2*)(y + (size_t)s1 * 64 + c);
            a0.x += v0.x; a0.y += v0.y;
            a1.x += v1.x; a1.y += v1.y;
        }
        if (t < n) {
            int s0 = __shfl_sync(0xffffffffu, sreg, t);
            float2 v0 = *(const float2*)(y + (size_t)s0 * 64 + c);
            a0.x += v0.x; a0.y += v0.y;
        }
    }
    float d = dinv[warp];
    float2 o;
    o.x = fmaxf(d * (a0.x + a1.x) + b[c],     0.0f);
    o.y = fmaxf(d * (a0.y + a1.y) + b[c + 1], 0.0f);
    *(float2*)(h + (size_t)warp * 64 + c) = o;
}

// ---------------- f32x2-packed fp32 GEMM (4 rows x 4 cols / thread) --------
// OUT[N,M] = post( scale?(dinv[row]) * (X[N,K] @ W[K,M]) + bias? ), relu?
// DUAL: X row = concat(X0 row [64], X1 row [64]) (K must be 128)
// X is staged TRANSPOSED in smem: Xs[k * XP + r], so a row-pair (r, r+1) for
// fixed k is one natural 8-byte load -> packed f32x2 operand, no pack instr.
template<int K, int M, bool DUAL, bool PRESCALE, bool BIAS, bool RELU>
__global__ void __launch_bounds__(256)
k_gemm(const float* __restrict__ X0, const float* __restrict__ X1,
       const float* __restrict__ W,  const float* __restrict__ bias,
       const float* __restrict__ dinv, float* __restrict__ OUT, int N) {
    constexpr int CG   = M / 4;          // col groups (4 cols per thread)
    constexpr int RG   = 256 / CG;       // row groups (4 rows per thread)
    constexpr int TILE = RG * 4;         // rows per block tile
    constexpr int XP   = TILE + 2;       // padded (even) transposed stride

    extern __shared__ float sm[];
    float* Ws = sm;                      // K*M
    float* Xs = sm + K * M;              // K * XP (transposed)

    for (int i = threadIdx.x; i < K * M; i += 256) Ws[i] = W[i];
    __syncthreads();

    const int cg  = threadIdx.x % CG;
    const int rg4 = (threadIdx.x / CG) * 4;
    const int numTiles = (N + TILE - 1) / TILE;

    for (int tile = blockIdx.x; tile < numTiles; tile += gridDim.x) {
        const int row0 = tile * TILE;
        // stage X tile transposed: coalesced global read, Xs[c*XP + r]
        for (int i = threadIdx.x; i < TILE * K; i += 256) {
            int r = i / K, c = i % K;
            int gr = row0 + r;
            float v = 0.f;
            if (gr < N) {
                if (!DUAL) v = X0[(size_t)gr * K + c];
                else       v = (c < 64) ? X0[(size_t)gr * 64 + c]
                                        : X1[(size_t)gr * 64 + (c - 64)];
            }
            Xs[c * XP + r] = v;
        }
        __syncthreads();

        unsigned long long a01[4], a23[4];
        #pragma unroll
        for (int q = 0; q < 4; ++q) { a01[q] = 0ull; a23[q] = 0ull; }

        const float* xbase = Xs + rg4;
        const float* wbase = Ws + cg * 4;

        #pragma unroll 8
        for (int k = 0; k < K; ++k) {
            unsigned long long X01 = *(const unsigned long long*)(xbase + k * XP);
            unsigned long long X23 = *(const unsigned long long*)(xbase + k * XP + 2);
            float4 w = *(const float4*)(wbase + k * M);
            unsigned long long W0 = pack2(w.x, w.x);
            unsigned long long W1 = pack2(w.y, w.y);
            unsigned long long W2 = pack2(w.z, w.z);
            unsigned long long W3 = pack2(w.w, w.w);
            a01[0] = fma2(X01, W0, a01[0]);
            a01[1] = fma2(X01, W1, a01[1]);
            a01[2] = fma2(X01, W2, a01[2]);
            a01[3] = fma2(X01, W3, a01[3]);
            a23[0] = fma2(X23, W0, a23[0]);
            a23[1] = fma2(X23, W1, a23[1]);
            a23[2] = fma2(X23, W2, a23[2]);
            a23[3] = fma2(X23, W3, a23[3]);
        }

        float v[4][4];
        #pragma unroll
        for (int q = 0; q < 4; ++q) {
            unpack2(a01[q], v[0][q], v[1][q]);
            unpack2(a23[q], v[2][q], v[3][q]);
        }

        #pragma unroll
        for (int j = 0; j < 4; ++j) {
            int gr = row0 + rg4 + j;
            if (gr >= N) continue;
            float4 o;
            o.x = v[j][0]; o.y = v[j][1]; o.z = v[j][2]; o.w = v[j][3];
            if (PRESCALE) {
                float s = dinv[gr];
                o.x *= s; o.y *= s; o.z *= s; o.w *= s;
            }
            if (BIAS) {
                float4 b4 = *(const float4*)(bias + cg * 4);
                o.x += b4.x; o.y += b4.y; o.z += b4.z; o.w += b4.w;
            }
            if (RELU) {
                o.x = fmaxf(o.x, 0.f); o.y = fmaxf(o.y, 0.f);
                o.z = fmaxf(o.z, 0.f); o.w = fmaxf(o.w, 0.f);
            }
            *(float4*)(OUT + (size_t)gr * M + cg * 4) = o;
        }
        __syncthreads();
    }
}

// ---------------- JAX partitionable threefry2x32 (key = [0, 42]) ----------
__device__ __forceinline__ unsigned rotl32(unsigned v, int r) {
    return (v << r) | (v >> (32 - r));
}

__device__ __forceinline__ uint2 threefry(unsigned c0, unsigned c1) {
    const unsigned k0 = 0u, k1 = 42u;
    const unsigned k2 = k0 ^ k1 ^ 0x1BD11BDAu;
    unsigned x0 = c0 + k0, x1 = c1 + k1;
#define TF_RND(r) { x0 += x1; x1 = rotl32(x1, r); x1 ^= x0; }
    TF_RND(13) TF_RND(15) TF_RND(26) TF_RND(6)
    x0 += k1; x1 += k2 + 1u;
    TF_RND(17) TF_RND(29) TF_RND(16) TF_RND(24)
    x0 += k2; x1 += k0 + 2u;
    TF_RND(13) TF_RND(15) TF_RND(26) TF_RND(6)
    x0 += k0; x1 += k1 + 3u;
    TF_RND(17) TF_RND(29) TF_RND(16) TF_RND(24)
    x0 += k1; x1 += k2 + 4u;
    TF_RND(13) TF_RND(15) TF_RND(26) TF_RND(6)
    x0 += k2; x1 += k0 + 5u;
#undef TF_RND
    return make_uint2(x0, x1);
}

__device__ __forceinline__ unsigned tf_bits_part(unsigned i) {
    uint2 o = threefry(0u, i);
    return o.x ^ o.y;
}

__device__ __forceinline__ float bits_to_uniform(unsigned b) {
    float f = __uint_as_float((b >> 9) | 0x3f800000u) - 1.0f;
    f = f + 1e-20f;
    return fmaxf(f, 1e-20f);
}

// ---------------- final: t2 @ Wo + bo -> sigmoid -> gumbel hard sample -----
__global__ void k_final(const float* __restrict__ t2, const float* __restrict__ Wo,
                        const float* __restrict__ bo, float* __restrict__ out, int N) {
    __shared__ float ws[64];
    if (threadIdx.x < 64) ws[threadIdx.x] = Wo[threadIdx.x];
    __syncthreads();

    int warp = (blockIdx.x * blockDim.x + threadIdx.x) >> 5;
    int lane = threadIdx.x & 31;
    if (warp >= N) return;

    const float* row = t2 + (size_t)warp * 64;
    float s = row[lane] * ws[lane] + row[lane + 32] * ws[lane + 32];
    #pragma unroll
    for (int o = 16; o; o >>= 1) s += __shfl_xor_sync(0xffffffffu, s, o);

    float p = 1.0f / (1.0f + expf(-(s + bo[0])));

    float g = 0.0f;
    if (lane < 2) {
        unsigned f = 2u * (unsigned)warp + (unsigned)lane;
        float u = bits_to_uniform(tf_bits_part(f));
        g = -logf(-logf(u));
    }
    float g0 = __shfl_sync(0xffffffffu, g, 0);
    float g1 = __shfl_sync(0xffffffffu, g, 1);

    if (lane == 0) {
        out[warp]     = p;
        out[N + warp] = ((p + g1) > ((1.0f - p) + g0)) ? 1.0f : 0.0f;
    }
}

// ---------------- launch ----------------
extern "C" void kernel_launch(void* const* d_in, const int* in_sizes, int n_in,
                              void* d_out, int out_size) {
    const float* rep = (const float*)d_in[0];
    const int*   ei  = (const int*)  d_in[1];
    const float* W1  = (const float*)d_in[2];
    const float* b1  = (const float*)d_in[3];
    const float* W2  = (const float*)d_in[4];
    const float* b2  = (const float*)d_in[5];
    const float* Wa  = (const float*)d_in[6];
    const float* ba  = (const float*)d_in[7];
    const float* Wb  = (const float*)d_in[8];
    const float* bb  = (const float*)d_in[9];
    const float* Wo  = (const float*)d_in[10];
    const float* bo  = (const float*)d_in[11];
    float* out = (float*)d_out;

    int N = in_sizes[0] / 64;
    int E = in_sizes[1] / 2;
    if (N > N_MAX || E > E_MAX) return;
    const int* src = ei;
    const int* dst = ei + E;

    float *dinv, *y, *h, *t1, *t2;
    int *cnt, *rp, *wp, *eidx, *bsum;
    cudaGetSymbolAddress((void**)&dinv, g_deg);
    cudaGetSymbolAddress((void**)&y,    g_y);
    cudaGetSymbolAddress((void**)&h,    g_h);
    cudaGetSymbolAddress((void**)&t1,   g_t1);
    cudaGetSymbolAddress((void**)&t2,   g_t2);
    cudaGetSymbolAddress((void**)&cnt,  g_cnt);
    cudaGetSymbolAddress((void**)&rp,   g_rp);
    cudaGetSymbolAddress((void**)&wp,   g_wp);
    cudaGetSymbolAddress((void**)&eidx, g_eidx);
    cudaGetSymbolAddress((void**)&bsum, g_bsum);

    // dynamic smem: Ws K*M + Xs K*(TILE+2)
    const int SM_G64  = (64 * 64   + 64  * 66) * 4;   // ~33 KB  (TILE=64)
    const int SM_MLP1 = (128 * 128 + 128 * 34) * 4;   // ~81 KB  (TILE=32)
    const int SM_MLP2 = (128 * 64  + 128 * 66) * 4;   // ~65 KB  (TILE=64)
    cudaFuncSetAttribute((const void*)k_gemm<64,64,false,true,false,false>,
                         cudaFuncAttributeMaxDynamicSharedMemorySize, SM_G64);
    cudaFuncSetAttribute((const void*)k_gemm<128,128,true ,false,true ,true >,
                         cudaFuncAttributeMaxDynamicSharedMemorySize, SM_MLP1);
    cudaFuncSetAttribute((const void*)k_gemm<128,64 ,false,false,true ,true >,
                         cudaFuncAttributeMaxDynamicSharedMemorySize, SM_MLP2);

    const int TB = 256;
    int gN    = (N + TB - 1) / TB;
    int gEdge = (E + TB - 1) / TB;
    int nB    = (N + 1023) / 1024;
    int gWarp = (N * 32 + TB - 1) / TB;

    // ---- CSR build (also yields exact degree -> dinv) ----
    k_zero <<<gN,    TB>>>(cnt, N);
    k_hist <<<gEdge, TB>>>(dst, cnt, E);
    k_scan1<<<nB,    256>>>(cnt, rp, bsum, N);
    k_scan2<<<1,     128>>>(bsum, nB);
    k_scan3<<<gN,    TB>>>(cnt, rp, wp, dinv, bsum, N, E);
    k_fill <<<gEdge, TB>>>(src, dst, wp, eidx, E);

    int tiles64 = (N + 63) / 64;
    int grid64  = tiles64 < 1480 ? tiles64 : 1480;

    // ---- GCN layer 1 ----
    k_gemm<64,64,false,true,false,false><<<grid64, TB, SM_G64>>>(rep, nullptr, W1, nullptr, dinv, y, N);
    k_gather<<<gWarp, TB>>>(y, rp, eidx, dinv, b1, h, N);

    // ---- GCN layer 2 ----
    k_gemm<64,64,false,true,false,false><<<grid64, TB, SM_G64>>>(h, nullptr, W2, nullptr, dinv, y, N);
    k_gather<<<gWarp, TB>>>(y, rp, eidx, dinv, b2, h, N);

    // ---- MLP head: z = [rep, h2] ----
    k_gemm<128,128,true ,false,true,true><<<296, TB, SM_MLP1>>>(rep, h, Wa, ba, nullptr, t1, N);
    k_gemm<128,64 ,false,false,true,true><<<444, TB, SM_MLP2>>>(t1, nullptr, Wb, bb, nullptr, t2, N);

    // ---- final projection + sigmoid + gumbel straight-through ----
    int gFin = (N + 7) / 8;
    k_final<<<gFin, TB>>>(t2, Wo, bo, out, N);
}